// round 16
// baseline (speedup 1.0000x reference)
#include <cuda_runtime.h>

// Decoder: y_{t+1} = y_t + cutoff * tanh(dt * MLP_b(y_t) / cutoff), per-batch weights.
// Mixed-precision prop layers: layer0 = fp32 straight from the input tensor (1.5
// inst/MAC, no dequant), layer1 = int16+per-row-scale (half the bytes, PRMT dequant,
// 8-row deferred bias correction). Balances the issue pipe (int16 tax) against the
// L1 wavefront pipe (fp32 tax). 256x256 persistent CTAs, exact ReLU sparsity via
// ballot compaction, transposed in_s (4x LDS.128 input layer). tanhf kept (saturation
// is load-bearing: u=dt*f/cut reaches O(1) late in the trajectory).

#define NB 256
#define NC 16
#define NH 256
#define NT 1000
#define TB 8

// Quantized layer-1 prop weights: biased uint16 (int16 + 32768), layout [b][k][j].
__device__ __align__(16) unsigned short g_pwq[(size_t)NB * NH * NH];
__device__ float g_scl[NB * NH];   // per-row scale s = rowmax/32767

// ---- dequant helpers ----
__device__ __forceinline__ float cvlo_b(unsigned u)
{   // u16 placed in mantissa of 2^23 -> exact float 2^23 + u
    return __uint_as_float(__byte_perm(u, 0x4B000000u, 0x7410));
}
__device__ __forceinline__ float cvhi_b(unsigned u)
{
    return __uint_as_float(__byte_perm(u, 0x4B000000u, 0x7432));
}
__device__ __forceinline__ float cvlo(unsigned u) { return cvlo_b(u) - 8421376.0f; }
__device__ __forceinline__ float cvhi(unsigned u) { return cvhi_b(u) - 8421376.0f; }

// biased row FMA: 8 outputs, FFMA only (bias removed later).
__device__ __forceinline__ void rowfma_b(float e, uint4 w, float a[8])
{
    a[0] = fmaf(e, cvlo_b(w.x), a[0]);
    a[1] = fmaf(e, cvhi_b(w.x), a[1]);
    a[2] = fmaf(e, cvlo_b(w.y), a[2]);
    a[3] = fmaf(e, cvhi_b(w.y), a[3]);
    a[4] = fmaf(e, cvlo_b(w.z), a[4]);
    a[5] = fmaf(e, cvhi_b(w.z), a[5]);
    a[6] = fmaf(e, cvlo_b(w.w), a[6]);
    a[7] = fmaf(e, cvhi_b(w.w), a[7]);
}
// remove accumulated bias for a row group with activation-sum es (FFMA-imm).
__device__ __forceinline__ void corr(float es, float a[8])
{
#pragma unroll
    for (int j = 0; j < 8; j++)
        a[j] = fmaf(es, -8421376.0f, a[j]);
}
// exact row FMA for tail rows.
__device__ __forceinline__ void rowfma(float e, uint4 w, float a[8])
{
    a[0] = fmaf(e, cvlo(w.x), a[0]);
    a[1] = fmaf(e, cvhi(w.x), a[1]);
    a[2] = fmaf(e, cvlo(w.y), a[2]);
    a[3] = fmaf(e, cvhi(w.y), a[3]);
    a[4] = fmaf(e, cvlo(w.z), a[4]);
    a[5] = fmaf(e, cvhi(w.z), a[5]);
    a[6] = fmaf(e, cvlo(w.w), a[6]);
    a[7] = fmaf(e, cvhi(w.w), a[7]);
}
// fp32 row FMA: two contiguous float4 segments.
__device__ __forceinline__ void rowfma_f(float e, float4 wa, float4 wb, float a[8])
{
    a[0] = fmaf(e, wa.x, a[0]);
    a[1] = fmaf(e, wa.y, a[1]);
    a[2] = fmaf(e, wa.z, a[2]);
    a[3] = fmaf(e, wa.w, a[3]);
    a[4] = fmaf(e, wb.x, a[4]);
    a[5] = fmaf(e, wb.y, a[5]);
    a[6] = fmaf(e, wb.z, a[6]);
    a[7] = fmaf(e, wb.w, a[7]);
}

// ---- pre-pass: quantize layer-1 only, 32 rows per block ----
__global__ __launch_bounds__(256)
void quant_kernel(const float* __restrict__ pw)
{
    __shared__ float buf[32 * NH];            // 32 KB
    const int blk = blockIdx.x;               // NB*8 = 2048 blocks
    const int rb  = blk & 7;                  // 32-row block within matrix
    const int bq  = blk >> 3;                 // batch
    const float* src = pw + ((size_t)bq * 2 + 1) * NH * NH + (size_t)rb * 32 * NH;
    const int tid = threadIdx.x;

    for (int idx = tid; idx < 32 * NH / 4; idx += 256)
        reinterpret_cast<float4*>(buf)[idx] =
            reinterpret_cast<const float4*>(src)[idx];
    __syncthreads();

    const int lane = tid & 31;
    const int wrp  = tid >> 5;
#pragma unroll
    for (int r = wrp * 4; r < wrp * 4 + 4; r++) {
        float mx = 0.f;
        for (int j = lane; j < NH; j += 32)
            mx = fmaxf(mx, fabsf(buf[r * NH + j]));
#pragma unroll
        for (int o = 16; o; o >>= 1)
            mx = fmaxf(mx, __shfl_xor_sync(0xffffffffu, mx, o));
        const float inv = (mx > 0.f) ? 32767.f / mx : 0.f;
        const int grow = rb * 32 + r;
        if (lane == 0)
            g_scl[bq * NH + grow] = (mx > 0.f) ? mx / 32767.f : 0.f;
        unsigned q[4];
#pragma unroll
        for (int p = 0; p < 4; p++) {
            int j = lane * 8 + p * 2;
            int va = __float2int_rn(buf[r * NH + j]     * inv);
            int vb = __float2int_rn(buf[r * NH + j + 1] * inv);
            va = max(-32767, min(32767, va)) + 32768;
            vb = max(-32767, min(32767, vb)) + 32768;
            q[p] = (unsigned)va | ((unsigned)vb << 16);
        }
        uint4 pack;
        pack.x = q[0]; pack.y = q[1]; pack.z = q[2]; pack.w = q[3];
        *reinterpret_cast<uint4*>(
            &g_pwq[((size_t)bq * NH + grow) * NH + lane * 8]) = pack;
    }
}

__global__ __launch_bounds__(256, 2)
void decoder_kernel(const float* __restrict__ y0,
                    const float* __restrict__ in_w,    // [B, C, H]
                    const float* __restrict__ in_b,    // [B, H]
                    const float* __restrict__ out_w,   // [B, H, C]
                    const float* __restrict__ out_b,   // [B, C]
                    const float* __restrict__ pw,      // [B, 2, H, H]
                    const float* __restrict__ pb,      // [B, 2, H]
                    const float* __restrict__ cutoff,  // [1]
                    float* __restrict__ out)           // [B, C, T]
{
    __shared__ __align__(16) float in_s[NH * NC];   // TRANSPOSED: [i][c]
    __shared__ float  out_s[NH * NC];    // [k][c]
    __shared__ float2 act[NH];           // compacted (value, row byte-offset bits)
    __shared__ __align__(16) int cnt_s[8];
    __shared__ __align__(16) float ys[NC];
    __shared__ float  po8[8 * NH];       // [group 0..7][output i] partials
    __shared__ float  po_s[256];         // out-layer partials [g16][c]
    __shared__ float  stage[NC][TB];

    const int b    = blockIdx.x;
    const int i    = threadIdx.x;
    const int lane = i & 31;
    const int wid  = i >> 5;   // warp = row group 0..7

    // ---- preload per-batch small weights into SMEM ----
    const float* inwb  = in_w  + (size_t)b * NC * NH;
    const float* outwb = out_w + (size_t)b * NH * NC;

#pragma unroll
    for (int c = 0; c < NC; c++)
        in_s[i * NC + c] = inwb[c * NH + i];    // transpose into [i][c]

#pragma unroll
    for (int q = 0; q < 4; q++) {
        float4 v = *reinterpret_cast<const float4*>(outwb + i * NC + q * 4);
        *reinterpret_cast<float4*>(&out_s[i * NC + q * 4]) = v;
    }

    const float bin = in_b[(size_t)b * NH + i];
    const float bp0 = pb[(size_t)b * 2 * NH + i];
    const float bp1 = pb[(size_t)b * 2 * NH + NH + i];
    const float ob  = (i < NC) ? out_b[(size_t)b * NC + i] : 0.f;
    const float cut = cutoff[0];
    const float rcut = 1.0f / cut;
    const float dt  = 1e-6f;
    const float s1r = g_scl[b * NH + i];   // layer-1 row scale for unit i

    if (i < NC) ys[i] = y0[(size_t)b * NC + i];

    const float*          pwf0 = pw + (size_t)b * 2 * NH * NH;      // layer0 fp32
    const unsigned short* pwq1 = &g_pwq[(size_t)b * NH * NH];       // layer1 int16
    float* outg = out + (size_t)b * NC * NT;

    int na = 0;  // active count (uniform across CTA after compact)

    // Deterministic compaction; vectorized count read (2x LDS.128).
    auto compact = [&](float rawh, float storeval, int koffbits) {
        bool nz = rawh > 0.f;
        unsigned bal = __ballot_sync(0xffffffffu, nz);
        if (lane == 0) cnt_s[wid] = __popc(bal);
        __syncthreads();
        int4 c0 = *reinterpret_cast<const int4*>(&cnt_s[0]);
        int4 c1 = *reinterpret_cast<const int4*>(&cnt_s[4]);
        na = ((c0.x + c0.y) + (c0.z + c0.w)) + ((c1.x + c1.y) + (c1.z + c1.w));
        int base = 0;
        if (wid > 0) base += c0.x;
        if (wid > 1) base += c0.y;
        if (wid > 2) base += c0.z;
        if (wid > 3) base += c0.w;
        if (wid > 4) base += c1.x;
        if (wid > 5) base += c1.y;
        if (wid > 6) base += c1.z;
        if (nz) {
            int pos = base + __popc(bal & ((1u << lane) - 1u));
            act[pos] = make_float2(storeval, __int_as_float(koffbits));
        }
        __syncthreads();
    };

    // 8-way cross-group reduce + relu; then compact with caller's encoding.
    auto reduce_compact = [&](float bias, float scale, int shift) {
        __syncthreads();
        float h = bias;
#pragma unroll
        for (int g = 0; g < 8; g++) h += po8[g * NH + i];
        h = fmaxf(h, 0.f);
        compact(h, h * scale, i << shift);
    };

    // Layer 0: fp32 rows straight from pw (1KB rows). Warp wid owns rows m ≡ wid
    // (mod 8); thread owns outputs [lane*4..+3] (a0..3) and [128+lane*4..+3] (a4..7).
    // Per row: one address, LDG.128 [p] and [p+512]; warp covers the row contiguously.
    auto prop_layer_f32 = [&]() {
        const char* bo = reinterpret_cast<const char*>(pwf0) + (size_t)(lane * 16);
        float a[8];
#pragma unroll
        for (int z = 0; z < 8; z++) a[z] = 0.f;
        int m = wid;
        for (; m + 56 < na; m += 64) {
            float2 e0 = act[m +  0], e1 = act[m +  8], e2 = act[m + 16], e3 = act[m + 24];
            float2 e4 = act[m + 32], e5 = act[m + 40], e6 = act[m + 48], e7 = act[m + 56];
            const char* p0 = bo + __float_as_int(e0.y);
            const char* p1 = bo + __float_as_int(e1.y);
            const char* p2 = bo + __float_as_int(e2.y);
            const char* p3 = bo + __float_as_int(e3.y);
            const char* p4 = bo + __float_as_int(e4.y);
            const char* p5 = bo + __float_as_int(e5.y);
            const char* p6 = bo + __float_as_int(e6.y);
            const char* p7 = bo + __float_as_int(e7.y);
            rowfma_f(e0.x, *reinterpret_cast<const float4*>(p0),
                           *reinterpret_cast<const float4*>(p0 + 512), a);
            rowfma_f(e1.x, *reinterpret_cast<const float4*>(p1),
                           *reinterpret_cast<const float4*>(p1 + 512), a);
            rowfma_f(e2.x, *reinterpret_cast<const float4*>(p2),
                           *reinterpret_cast<const float4*>(p2 + 512), a);
            rowfma_f(e3.x, *reinterpret_cast<const float4*>(p3),
                           *reinterpret_cast<const float4*>(p3 + 512), a);
            rowfma_f(e4.x, *reinterpret_cast<const float4*>(p4),
                           *reinterpret_cast<const float4*>(p4 + 512), a);
            rowfma_f(e5.x, *reinterpret_cast<const float4*>(p5),
                           *reinterpret_cast<const float4*>(p5 + 512), a);
            rowfma_f(e6.x, *reinterpret_cast<const float4*>(p6),
                           *reinterpret_cast<const float4*>(p6 + 512), a);
            rowfma_f(e7.x, *reinterpret_cast<const float4*>(p7),
                           *reinterpret_cast<const float4*>(p7 + 512), a);
        }
        for (; m < na; m += 8) {
            float2 e = act[m];
            const char* p = bo + __float_as_int(e.y);
            rowfma_f(e.x, *reinterpret_cast<const float4*>(p),
                          *reinterpret_cast<const float4*>(p + 512), a);
        }
        // partials: a0..3 -> outputs lane*4..+3 ; a4..7 -> outputs 128+lane*4..+3
        float* dst = &po8[wid * NH + lane * 4];
        float4 lo; lo.x = a[0]; lo.y = a[1]; lo.z = a[2]; lo.w = a[3];
        float4 hi; hi.x = a[4]; hi.y = a[5]; hi.z = a[6]; hi.w = a[7];
        *reinterpret_cast<float4*>(dst)       = lo;
        *reinterpret_cast<float4*>(dst + 128) = hi;
        reduce_compact(bp0, s1r, 9);   // feeds int16 layer (512B rows)
    };

    // Layer 1: int16, software-pipelined 4-row chunks, bias correction per 8 rows.
    // Thread owns outputs [lane*8 .. lane*8+7]; one LDG.128 per (thread,row).
    auto prop_layer_i16 = [&]() {
        const char* bo = reinterpret_cast<const char*>(pwq1) + (size_t)(lane * 16);
        float a[8];
#pragma unroll
        for (int z = 0; z < 8; z++) a[z] = 0.f;

        float2 eA[4], eB[4];
        uint4  wA[4], wB[4];
        int m = wid;

        if (m + 24 < na) {
#pragma unroll
            for (int z = 0; z < 4; z++) eA[z] = act[m + z * 8];
#pragma unroll
            for (int z = 0; z < 4; z++)
                wA[z] = *reinterpret_cast<const uint4*>(bo + __float_as_int(eA[z].y));
            while (true) {
                int mB = m + 32;
                if (mB + 24 < na) {
#pragma unroll
                    for (int z = 0; z < 4; z++) eB[z] = act[mB + z * 8];
#pragma unroll
                    for (int z = 0; z < 4; z++)
                        wB[z] = *reinterpret_cast<const uint4*>(bo + __float_as_int(eB[z].y));
                    rowfma_b(eA[0].x, wA[0], a);
                    rowfma_b(eA[1].x, wA[1], a);
                    rowfma_b(eA[2].x, wA[2], a);
                    rowfma_b(eA[3].x, wA[3], a);
                    float esA = (eA[0].x + eA[1].x) + (eA[2].x + eA[3].x);
                    int mA2 = mB + 32;
                    if (mA2 + 24 < na) {
#pragma unroll
                        for (int z = 0; z < 4; z++) eA[z] = act[mA2 + z * 8];
#pragma unroll
                        for (int z = 0; z < 4; z++)
                            wA[z] = *reinterpret_cast<const uint4*>(bo + __float_as_int(eA[z].y));
                        rowfma_b(eB[0].x, wB[0], a);
                        rowfma_b(eB[1].x, wB[1], a);
                        rowfma_b(eB[2].x, wB[2], a);
                        rowfma_b(eB[3].x, wB[3], a);
                        corr(esA + ((eB[0].x + eB[1].x) + (eB[2].x + eB[3].x)), a);
                        m = mA2;
                        continue;
                    }
                    rowfma_b(eB[0].x, wB[0], a);
                    rowfma_b(eB[1].x, wB[1], a);
                    rowfma_b(eB[2].x, wB[2], a);
                    rowfma_b(eB[3].x, wB[3], a);
                    corr(esA + ((eB[0].x + eB[1].x) + (eB[2].x + eB[3].x)), a);
                    m = mB + 32;
                    break;
                }
                rowfma_b(eA[0].x, wA[0], a);
                rowfma_b(eA[1].x, wA[1], a);
                rowfma_b(eA[2].x, wA[2], a);
                rowfma_b(eA[3].x, wA[3], a);
                corr((eA[0].x + eA[1].x) + (eA[2].x + eA[3].x), a);
                m = mB;
                break;
            }
        }
        for (; m < na; m += 8) {   // exact tail
            float2 e = act[m];
            uint4  w = *reinterpret_cast<const uint4*>(bo + __float_as_int(e.y));
            rowfma(e.x, w, a);
        }

        float* dst = &po8[wid * NH + lane * 8];
        float4 lo; lo.x = a[0]; lo.y = a[1]; lo.z = a[2]; lo.w = a[3];
        float4 hi; hi.x = a[4]; hi.y = a[5]; hi.z = a[6]; hi.w = a[7];
        *reinterpret_cast<float4*>(dst)     = lo;
        *reinterpret_cast<float4*>(dst + 4) = hi;
        reduce_compact(bp1, 1.0f, 10);   // raw, feeds fp32 out_s (bits>>6 indexing)
    };

    __syncthreads();

    for (int t = 0; t < NT; t++) {
        // ---- input layer (transposed in_s: 4x LDS.128 per thread) ----
        const float4* ysv = reinterpret_cast<const float4*>(ys);
        float4 y0v = ysv[0], y1v = ysv[1], y2v = ysv[2], y3v = ysv[3];
        const float4* wv = reinterpret_cast<const float4*>(&in_s[i * NC]);
        float4 w0 = wv[0], w1 = wv[1], w2 = wv[2], w3 = wv[3];
        float acc = bin;
        acc = fmaf(y0v.x, w0.x, acc);
        acc = fmaf(y0v.y, w0.y, acc);
        acc = fmaf(y0v.z, w0.z, acc);
        acc = fmaf(y0v.w, w0.w, acc);
        acc = fmaf(y1v.x, w1.x, acc);
        acc = fmaf(y1v.y, w1.y, acc);
        acc = fmaf(y1v.z, w1.z, acc);
        acc = fmaf(y1v.w, w1.w, acc);
        acc = fmaf(y2v.x, w2.x, acc);
        acc = fmaf(y2v.y, w2.y, acc);
        acc = fmaf(y2v.z, w2.z, acc);
        acc = fmaf(y2v.w, w2.w, acc);
        acc = fmaf(y3v.x, w3.x, acc);
        acc = fmaf(y3v.y, w3.y, acc);
        acc = fmaf(y3v.z, w3.z, acc);
        acc = fmaf(y3v.w, w3.w, acc);
        acc = fmaxf(acc, 0.f);
        compact(acc, acc, i << 10);   // raw h, fp32 row stride = 1024 B

        // ---- prop layer 0 (fp32) then layer 1 (int16) ----
        prop_layer_f32();
        prop_layer_i16();

        // ---- output layer (SMEM, sparse over k) ----
        {
            int c = i & 15, g16 = i >> 4;
            float p = 0.f;
            for (int m = g16; m < na; m += 16) {
                float2 e = act[m];
                // koffbits = k<<10 -> out_s index k*16 + c = (bits>>6) + c
                p = fmaf(e.x, out_s[(__float_as_int(e.y) >> 6) + c], p);
            }
            po_s[i] = p;
        }
        __syncthreads();

        if (i < NC) {
            float f = ob;
#pragma unroll
            for (int g16 = 0; g16 < 16; g16++) f += po_s[g16 * 16 + i];
            // tanh saturation required: u reaches O(1) late in trajectory.
            float yn = ys[i] + cut * tanhf(dt * f * rcut);
            ys[i] = yn;
            stage[i][t & (TB - 1)] = yn;
        }
        __syncthreads();

        // coalesced flush every TB steps
        if ((t & (TB - 1)) == (TB - 1) && i < NC * TB) {
            int c = i >> 3, u = i & 7;
            outg[c * NT + (t - (TB - 1)) + u] = stage[c][u];
        }
    }
}

extern "C" void kernel_launch(void* const* d_in, const int* in_sizes, int n_in,
                              void* d_out, int out_size)
{
    (void)in_sizes; (void)n_in; (void)out_size;
    quant_kernel<<<NB * 8, 256>>>((const float*)d_in[5]);  // prop_weight layer 1 only
    decoder_kernel<<<NB, 256>>>(
        (const float*)d_in[0],   // y0
        (const float*)d_in[1],   // in_weight
        (const float*)d_in[2],   // in_bias
        (const float*)d_in[3],   // out_weight
        (const float*)d_in[4],   // out_bias
        (const float*)d_in[5],   // prop_weight (layer 0 fp32 direct)
        (const float*)d_in[6],   // prop_bias
        (const float*)d_in[7],   // cutoff
        (float*)d_out);
}

// round 17
// speedup vs baseline: 1.0734x; 1.0734x over previous
#include <cuda_runtime.h>

// Decoder: y_{t+1} = y_t + cutoff * tanh(dt * MLP_b(y_t) / cutoff), per-batch weights.
// R15 design (256x256 persistent CTAs, int16 prop weights + per-row fp32 scale,
// exact ReLU sparsity via ballot compaction, biased PRMT dequant, 8-row deferred
// bias correction, 2-stage software-pipelined mainloop) with:
//  - DENSE output layer: layer-1 result goes to hd[256]; third compact + one
//    __syncthreads eliminated; output reads are vectorized & conflict-free (pad 17)
//  - transposed in_s [i][c]: input layer via LDS.128
// tanhf kept (saturation is load-bearing late in the trajectory).

#define NB 256
#define NC 16
#define NH 256
#define NT 1000
#define TB 8

// Quantized prop weights: biased uint16 (int16 value + 32768), layout [b][l][k][j].
__device__ __align__(16) unsigned short g_pwq[(size_t)NB * 2 * NH * NH];
__device__ float g_scl[NB * 2 * NH];   // per-row scale s = rowmax/32767

// ---- dequant helpers ----
__device__ __forceinline__ float cvlo_b(unsigned u)
{   // u16 placed in mantissa of 2^23 -> exact float 2^23 + u
    return __uint_as_float(__byte_perm(u, 0x4B000000u, 0x7410));
}
__device__ __forceinline__ float cvhi_b(unsigned u)
{
    return __uint_as_float(__byte_perm(u, 0x4B000000u, 0x7432));
}
__device__ __forceinline__ float cvlo(unsigned u) { return cvlo_b(u) - 8421376.0f; }
__device__ __forceinline__ float cvhi(unsigned u) { return cvhi_b(u) - 8421376.0f; }

// biased row FMA: 8 outputs, FFMA only (bias removed later).
__device__ __forceinline__ void rowfma_b(float e, uint4 w, float a[8])
{
    a[0] = fmaf(e, cvlo_b(w.x), a[0]);
    a[1] = fmaf(e, cvhi_b(w.x), a[1]);
    a[2] = fmaf(e, cvlo_b(w.y), a[2]);
    a[3] = fmaf(e, cvhi_b(w.y), a[3]);
    a[4] = fmaf(e, cvlo_b(w.z), a[4]);
    a[5] = fmaf(e, cvhi_b(w.z), a[5]);
    a[6] = fmaf(e, cvlo_b(w.w), a[6]);
    a[7] = fmaf(e, cvhi_b(w.w), a[7]);
}
// remove accumulated bias for a row group with activation-sum es (FFMA-imm).
__device__ __forceinline__ void corr(float es, float a[8])
{
#pragma unroll
    for (int j = 0; j < 8; j++)
        a[j] = fmaf(es, -8421376.0f, a[j]);
}
// exact row FMA for tail rows.
__device__ __forceinline__ void rowfma(float e, uint4 w, float a[8])
{
    a[0] = fmaf(e, cvlo(w.x), a[0]);
    a[1] = fmaf(e, cvhi(w.x), a[1]);
    a[2] = fmaf(e, cvlo(w.y), a[2]);
    a[3] = fmaf(e, cvhi(w.y), a[3]);
    a[4] = fmaf(e, cvlo(w.z), a[4]);
    a[5] = fmaf(e, cvhi(w.z), a[5]);
    a[6] = fmaf(e, cvlo(w.w), a[6]);
    a[7] = fmaf(e, cvhi(w.w), a[7]);
}

// ---- pre-pass: quantize both prop layers, 32 rows per block ----
__global__ __launch_bounds__(256)
void quant_kernel(const float* __restrict__ pw)
{
    __shared__ float buf[32 * NH];            // 32 KB
    const int blk = blockIdx.x;               // NB*2*8 = 4096 blocks
    const int rb  = blk & 7;                  // 32-row block within matrix
    const int bl  = blk >> 3;                 // b*2 + l
    const float* src = pw + (size_t)bl * NH * NH + (size_t)rb * 32 * NH;
    const int tid = threadIdx.x;

    for (int idx = tid; idx < 32 * NH / 4; idx += 256)
        reinterpret_cast<float4*>(buf)[idx] =
            reinterpret_cast<const float4*>(src)[idx];
    __syncthreads();

    const int lane = tid & 31;
    const int wrp  = tid >> 5;
#pragma unroll
    for (int r = wrp * 4; r < wrp * 4 + 4; r++) {
        float mx = 0.f;
        for (int j = lane; j < NH; j += 32)
            mx = fmaxf(mx, fabsf(buf[r * NH + j]));
#pragma unroll
        for (int o = 16; o; o >>= 1)
            mx = fmaxf(mx, __shfl_xor_sync(0xffffffffu, mx, o));
        const float inv = (mx > 0.f) ? 32767.f / mx : 0.f;
        const int grow = rb * 32 + r;
        if (lane == 0)
            g_scl[bl * NH + grow] = (mx > 0.f) ? mx / 32767.f : 0.f;
        unsigned q[4];
#pragma unroll
        for (int p = 0; p < 4; p++) {
            int j = lane * 8 + p * 2;
            int va = __float2int_rn(buf[r * NH + j]     * inv);
            int vb = __float2int_rn(buf[r * NH + j + 1] * inv);
            va = max(-32767, min(32767, va)) + 32768;
            vb = max(-32767, min(32767, vb)) + 32768;
            q[p] = (unsigned)va | ((unsigned)vb << 16);
        }
        uint4 pack;
        pack.x = q[0]; pack.y = q[1]; pack.z = q[2]; pack.w = q[3];
        *reinterpret_cast<uint4*>(
            &g_pwq[((size_t)bl * NH + grow) * NH + lane * 8]) = pack;
    }
}

__global__ __launch_bounds__(256, 2)
void decoder_kernel(const float* __restrict__ y0,
                    const float* __restrict__ in_w,    // [B, C, H]
                    const float* __restrict__ in_b,    // [B, H]
                    const float* __restrict__ out_w,   // [B, H, C]
                    const float* __restrict__ out_b,   // [B, C]
                    const float* __restrict__ pb,      // [B, 2, H]
                    const float* __restrict__ cutoff,  // [1]
                    float* __restrict__ out)           // [B, C, T]
{
    __shared__ __align__(16) float in_s[NH * NC];   // TRANSPOSED: [i][c]
    __shared__ float  out_s[NH * 17];    // [k][c], stride 17 (conflict-free reads)
    __shared__ float2 act[NH];           // compacted (scaled h, row byte-offset bits)
    __shared__ __align__(16) int cnt_s[8];
    __shared__ __align__(16) float ys[NC];
    __shared__ float  po8[8 * NH];       // [group 0..7][output i] partials
    __shared__ float  po_s[256];         // out-layer partials [g16][c]
    __shared__ __align__(16) float hd[NH];  // dense layer-1 activations
    __shared__ float  stage[NC][TB];

    const int b    = blockIdx.x;
    const int i    = threadIdx.x;
    const int lane = i & 31;
    const int wid  = i >> 5;   // warp = row group 0..7

    // ---- preload per-batch small weights into SMEM ----
    const float* inwb  = in_w  + (size_t)b * NC * NH;
    const float* outwb = out_w + (size_t)b * NH * NC;

#pragma unroll
    for (int c = 0; c < NC; c++)
        in_s[i * NC + c] = inwb[c * NH + i];    // transpose into [i][c]

#pragma unroll
    for (int c = 0; c < NC; c++)
        out_s[i * 17 + c] = outwb[i * NC + c];  // padded stride 17

    const float bin = in_b[(size_t)b * NH + i];
    const float bp0 = pb[(size_t)b * 2 * NH + i];
    const float bp1 = pb[(size_t)b * 2 * NH + NH + i];
    const float ob  = (i < NC) ? out_b[(size_t)b * NC + i] : 0.f;
    const float cut = cutoff[0];
    const float rcut = 1.0f / cut;
    const float dt  = 1e-6f;
    const float s0r = g_scl[(b * 2 + 0) * NH + i];
    const float s1r = g_scl[(b * 2 + 1) * NH + i];

    if (i < NC) ys[i] = y0[(size_t)b * NC + i];

    const unsigned short* pwq0 = &g_pwq[(size_t)(b * 2 + 0) * NH * NH];
    const unsigned short* pwq1 = &g_pwq[(size_t)(b * 2 + 1) * NH * NH];
    float* outg = out + (size_t)b * NC * NT;

    int na = 0;  // active count (uniform across CTA after compact)

    // Deterministic compaction; vectorized count read (2x LDS.128).
    auto compact = [&](float rawh, float storeval, int koffbits) {
        bool nz = rawh > 0.f;
        unsigned bal = __ballot_sync(0xffffffffu, nz);
        if (lane == 0) cnt_s[wid] = __popc(bal);
        __syncthreads();
        int4 c0 = *reinterpret_cast<const int4*>(&cnt_s[0]);
        int4 c1 = *reinterpret_cast<const int4*>(&cnt_s[4]);
        na = ((c0.x + c0.y) + (c0.z + c0.w)) + ((c1.x + c1.y) + (c1.z + c1.w));
        int base = 0;
        if (wid > 0) base += c0.x;
        if (wid > 1) base += c0.y;
        if (wid > 2) base += c0.z;
        if (wid > 3) base += c0.w;
        if (wid > 4) base += c1.x;
        if (wid > 5) base += c1.y;
        if (wid > 6) base += c1.z;
        if (nz) {
            int pos = base + __popc(bal & ((1u << lane) - 1u));
            act[pos] = make_float2(storeval, __int_as_float(koffbits));
        }
        __syncthreads();
    };

    // Sparse int16 matvec mainloop (software-pipelined 4-row chunks, 8-row deferred
    // bias correction). Warp wid owns rows m ≡ wid (mod 8); thread owns outputs
    // [lane*8 .. lane*8+7]. Ends with po8 partial write (no sync).
    auto prop_main = [&](const unsigned short* wq) {
        const char* bo = reinterpret_cast<const char*>(wq) + (size_t)(lane * 16);
        float a[8];
#pragma unroll
        for (int z = 0; z < 8; z++) a[z] = 0.f;

        float2 eA[4], eB[4];
        uint4  wA[4], wB[4];
        int m = wid;

        if (m + 24 < na) {
#pragma unroll
            for (int z = 0; z < 4; z++) eA[z] = act[m + z * 8];
#pragma unroll
            for (int z = 0; z < 4; z++)
                wA[z] = *reinterpret_cast<const uint4*>(bo + __float_as_int(eA[z].y));
            while (true) {
                int mB = m + 32;
                if (mB + 24 < na) {
#pragma unroll
                    for (int z = 0; z < 4; z++) eB[z] = act[mB + z * 8];
#pragma unroll
                    for (int z = 0; z < 4; z++)
                        wB[z] = *reinterpret_cast<const uint4*>(bo + __float_as_int(eB[z].y));
                    rowfma_b(eA[0].x, wA[0], a);
                    rowfma_b(eA[1].x, wA[1], a);
                    rowfma_b(eA[2].x, wA[2], a);
                    rowfma_b(eA[3].x, wA[3], a);
                    float esA = (eA[0].x + eA[1].x) + (eA[2].x + eA[3].x);
                    int mA2 = mB + 32;
                    if (mA2 + 24 < na) {
#pragma unroll
                        for (int z = 0; z < 4; z++) eA[z] = act[mA2 + z * 8];
#pragma unroll
                        for (int z = 0; z < 4; z++)
                            wA[z] = *reinterpret_cast<const uint4*>(bo + __float_as_int(eA[z].y));
                        rowfma_b(eB[0].x, wB[0], a);
                        rowfma_b(eB[1].x, wB[1], a);
                        rowfma_b(eB[2].x, wB[2], a);
                        rowfma_b(eB[3].x, wB[3], a);
                        corr(esA + ((eB[0].x + eB[1].x) + (eB[2].x + eB[3].x)), a);
                        m = mA2;
                        continue;
                    }
                    rowfma_b(eB[0].x, wB[0], a);
                    rowfma_b(eB[1].x, wB[1], a);
                    rowfma_b(eB[2].x, wB[2], a);
                    rowfma_b(eB[3].x, wB[3], a);
                    corr(esA + ((eB[0].x + eB[1].x) + (eB[2].x + eB[3].x)), a);
                    m = mB + 32;
                    break;
                }
                rowfma_b(eA[0].x, wA[0], a);
                rowfma_b(eA[1].x, wA[1], a);
                rowfma_b(eA[2].x, wA[2], a);
                rowfma_b(eA[3].x, wA[3], a);
                corr((eA[0].x + eA[1].x) + (eA[2].x + eA[3].x), a);
                m = mB;
                break;
            }
        }
        for (; m < na; m += 8) {   // exact tail
            float2 e = act[m];
            uint4  w = *reinterpret_cast<const uint4*>(bo + __float_as_int(e.y));
            rowfma(e.x, w, a);
        }

        float* dst = &po8[wid * NH + lane * 8];
        float4 lo; lo.x = a[0]; lo.y = a[1]; lo.z = a[2]; lo.w = a[3];
        float4 hi; hi.x = a[4]; hi.y = a[5]; hi.z = a[6]; hi.w = a[7];
        *reinterpret_cast<float4*>(dst)     = lo;
        *reinterpret_cast<float4*>(dst + 4) = hi;
    };

    __syncthreads();

    for (int t = 0; t < NT; t++) {
        // ---- input layer (transposed in_s: 4x LDS.128 + 4x LDS.128) ----
        const float4* ysv = reinterpret_cast<const float4*>(ys);
        float4 y0v = ysv[0], y1v = ysv[1], y2v = ysv[2], y3v = ysv[3];
        const float4* wv = reinterpret_cast<const float4*>(&in_s[i * NC]);
        float4 w0 = wv[0], w1 = wv[1], w2 = wv[2], w3 = wv[3];
        float acc = bin;
        acc = fmaf(y0v.x, w0.x, acc);
        acc = fmaf(y0v.y, w0.y, acc);
        acc = fmaf(y0v.z, w0.z, acc);
        acc = fmaf(y0v.w, w0.w, acc);
        acc = fmaf(y1v.x, w1.x, acc);
        acc = fmaf(y1v.y, w1.y, acc);
        acc = fmaf(y1v.z, w1.z, acc);
        acc = fmaf(y1v.w, w1.w, acc);
        acc = fmaf(y2v.x, w2.x, acc);
        acc = fmaf(y2v.y, w2.y, acc);
        acc = fmaf(y2v.z, w2.z, acc);
        acc = fmaf(y2v.w, w2.w, acc);
        acc = fmaf(y3v.x, w3.x, acc);
        acc = fmaf(y3v.y, w3.y, acc);
        acc = fmaf(y3v.z, w3.z, acc);
        acc = fmaf(y3v.w, w3.w, acc);
        acc = fmaxf(acc, 0.f);
        compact(acc, acc * s0r, i << 9);   // int16 row stride = 512 B

        // ---- prop layer 0 (int16) -> compact for layer 1 ----
        prop_main(pwq0);
        __syncthreads();
        {
            float h = bp0;
#pragma unroll
            for (int g = 0; g < 8; g++) h += po8[g * NH + i];
            h = fmaxf(h, 0.f);
            compact(h, h * s1r, i << 9);
        }

        // ---- prop layer 1 (int16) -> DENSE hd (no compact) ----
        prop_main(pwq1);
        __syncthreads();
        {
            float h = bp1;
#pragma unroll
            for (int g = 0; g < 8; g++) h += po8[g * NH + i];
            hd[i] = fmaxf(h, 0.f);
        }
        __syncthreads();

        // ---- output layer (dense, vectorized hd reads, conflict-free out_s) ----
        {
            int c = i & 15, g = i >> 4;           // 16 groups x 16 channels
            const float4* hv = reinterpret_cast<const float4*>(&hd[g * 16]);
            float4 h0 = hv[0], h1 = hv[1], h2 = hv[2], h3 = hv[3];
            const float* os = &out_s[g * 16 * 17 + c];
            float p = 0.f;
            p = fmaf(h0.x, os[ 0 * 17], p);
            p = fmaf(h0.y, os[ 1 * 17], p);
            p = fmaf(h0.z, os[ 2 * 17], p);
            p = fmaf(h0.w, os[ 3 * 17], p);
            p = fmaf(h1.x, os[ 4 * 17], p);
            p = fmaf(h1.y, os[ 5 * 17], p);
            p = fmaf(h1.z, os[ 6 * 17], p);
            p = fmaf(h1.w, os[ 7 * 17], p);
            p = fmaf(h2.x, os[ 8 * 17], p);
            p = fmaf(h2.y, os[ 9 * 17], p);
            p = fmaf(h2.z, os[10 * 17], p);
            p = fmaf(h2.w, os[11 * 17], p);
            p = fmaf(h3.x, os[12 * 17], p);
            p = fmaf(h3.y, os[13 * 17], p);
            p = fmaf(h3.z, os[14 * 17], p);
            p = fmaf(h3.w, os[15 * 17], p);
            po_s[i] = p;
        }
        __syncthreads();

        if (i < NC) {
            float f = ob;
#pragma unroll
            for (int g16 = 0; g16 < 16; g16++) f += po_s[g16 * 16 + i];
            // tanh saturation required: u reaches O(1) late in trajectory.
            float yn = ys[i] + cut * tanhf(dt * f * rcut);
            ys[i] = yn;
            stage[i][t & (TB - 1)] = yn;
        }
        __syncthreads();

        // coalesced flush every TB steps
        if ((t & (TB - 1)) == (TB - 1) && i < NC * TB) {
            int c = i >> 3, u = i & 7;
            outg[c * NT + (t - (TB - 1)) + u] = stage[c][u];
        }
    }
}

extern "C" void kernel_launch(void* const* d_in, const int* in_sizes, int n_in,
                              void* d_out, int out_size)
{
    (void)in_sizes; (void)n_in; (void)out_size;
    quant_kernel<<<NB * 2 * 8, 256>>>((const float*)d_in[5]);  // prop_weight
    decoder_kernel<<<NB, 256>>>(
        (const float*)d_in[0],   // y0
        (const float*)d_in[1],   // in_weight
        (const float*)d_in[2],   // in_bias
        (const float*)d_in[3],   // out_weight
        (const float*)d_in[4],   // out_bias
        (const float*)d_in[6],   // prop_bias
        (const float*)d_in[7],   // cutoff
        (float*)d_out);
}